// round 13
// baseline (speedup 1.0000x reference)
#include <cuda_runtime.h>
#include <math.h>

#define BB   512
#define SS   512
#define OBSD 64
#define HH   128
#define M_ROWS (BB*SS)          // 262144
#define G4   (4*HH)             // 512

// output layout (fp32, return order: action, log_prob, value, h, c)
#define OFF_LP ((size_t)M_ROWS*9)
#define OFF_V  (OFF_LP + (size_t)M_ROWS)
#define OFF_H  (OFF_V + (size_t)M_ROWS)
#define OFF_C  (OFF_H + (size_t)2*BB*HH)

// static scratch (allowed: not runtime allocation)
__device__ float  g_A [(size_t)M_ROWS * G4];   // gi buffer
__device__ float  g_Bf[(size_t)M_ROWS * HH];   // y1 / enc / lstm_out
__device__ float  g_Cf[(size_t)M_ROWS * HH];   // ln_out / h0_all / t1|t2
__device__ float4 g_wq[2][32*512];             // packed whh per layer

__device__ __forceinline__ float sigmf(float x) { return 1.0f / (1.0f + expf(-x)); }

// ---------------------------------------------------------------------------
// fp32 GEMM: C[M,N] = act(X[M,K] @ W[N,K]^T + b1 (+b2)); BM=128 BN=64 BK=16
// ---------------------------------------------------------------------------
__global__ __launch_bounds__(256) void gemm_kernel(
    const float* __restrict__ X, const float* __restrict__ W,
    const float* __restrict__ b1, const float* __restrict__ b2,
    float* __restrict__ C, int M, int N, int K, int relu)
{
    __shared__ float Xs[16][128];
    __shared__ float Ws[16][64];
    const int t  = threadIdx.x;
    const int bm = blockIdx.y * 128;
    const int bn = blockIdx.x * 64;
    const int tx = t & 15, ty = t >> 4;

    float acc[8][4];
#pragma unroll
    for (int i = 0; i < 8; i++)
#pragma unroll
        for (int jj = 0; jj < 4; jj++) acc[i][jj] = 0.f;

    for (int k0 = 0; k0 < K; k0 += 16) {
#pragma unroll
        for (int q = t; q < 512; q += 256) {
            int m = q >> 2, kk = (q & 3) << 2;
            float4 v = *(const float4*)(X + (size_t)(bm + m) * K + k0 + kk);
            Xs[kk+0][m] = v.x; Xs[kk+1][m] = v.y; Xs[kk+2][m] = v.z; Xs[kk+3][m] = v.w;
        }
        {
            int n = t >> 2, kk = (t & 3) << 2;
            float4 v = *(const float4*)(W + (size_t)(bn + n) * K + k0 + kk);
            Ws[kk+0][n] = v.x; Ws[kk+1][n] = v.y; Ws[kk+2][n] = v.z; Ws[kk+3][n] = v.w;
        }
        __syncthreads();
#pragma unroll
        for (int kk = 0; kk < 16; kk++) {
            float a[8], w[4];
#pragma unroll
            for (int i = 0; i < 8; i++) a[i] = Xs[kk][ty * 8 + i];
#pragma unroll
            for (int jj = 0; jj < 4; jj++) w[jj] = Ws[kk][tx * 4 + jj];
#pragma unroll
            for (int i = 0; i < 8; i++)
#pragma unroll
                for (int jj = 0; jj < 4; jj++) acc[i][jj] += a[i] * w[jj];
        }
        __syncthreads();
    }
#pragma unroll
    for (int jj = 0; jj < 4; jj++) {
        int n = bn + tx * 4 + jj;
        float bias = __ldg(&b1[n]) + (b2 ? __ldg(&b2[n]) : 0.f);
#pragma unroll
        for (int i = 0; i < 8; i++) {
            float v = acc[i][jj] + bias;
            if (relu) v = fmaxf(v, 0.f);
            C[(size_t)(bm + ty * 8 + i) * N + n] = v;
        }
    }
}

// LayerNorm(128)+ReLU, one warp per row
__global__ __launch_bounds__(256) void ln_relu_kernel(
    const float* __restrict__ in, float* __restrict__ out,
    const float* __restrict__ gw, const float* __restrict__ bw)
{
    int warp = threadIdx.x >> 5, lane = threadIdx.x & 31;
    size_t row = (size_t)blockIdx.x * 8 + warp;
    float4 v = ((const float4*)(in + row * 128))[lane];
    float s  = v.x + v.y + v.z + v.w;
    float sq = v.x*v.x + v.y*v.y + v.z*v.z + v.w*v.w;
#pragma unroll
    for (int o = 16; o > 0; o >>= 1) {
        s  += __shfl_xor_sync(0xffffffffu, s,  o);
        sq += __shfl_xor_sync(0xffffffffu, sq, o);
    }
    float mean = s * (1.f / 128.f);
    float var  = sq * (1.f / 128.f) - mean * mean;
    float rstd = rsqrtf(var + 1e-5f);
    float4 g4 = __ldg((const float4*)gw + lane);
    float4 b4 = __ldg((const float4*)bw + lane);
    float4 o4;
    o4.x = fmaxf((v.x - mean) * rstd * g4.x + b4.x, 0.f);
    o4.y = fmaxf((v.y - mean) * rstd * g4.y + b4.y, 0.f);
    o4.z = fmaxf((v.z - mean) * rstd * g4.z + b4.z, 0.f);
    o4.w = fmaxf((v.w - mean) * rstd * g4.w + b4.w, 0.f);
    ((float4*)(out + row * 128))[lane] = o4;
}

// pack whh(512x128): wq[k4*512+j] = whh[j][4k4..4k4+3]
__global__ void pack_whh(const float* __restrict__ whh, float4* __restrict__ wq)
{
    int idx = blockIdx.x * 256 + threadIdx.x;    // 16384
    int k4 = idx & 31, jj = idx >> 5;
    wq[k4 * 512 + jj] = *(const float4*)(whh + (size_t)jj * 128 + k4 * 4);
}

// ---------------------------------------------------------------------------
// Sequential masked LSTM pass, one layer. 128 CTAs x 512 thr, 4 rows/CTA.
// ---------------------------------------------------------------------------
#define SK4 24
#define PASS_SMEM (SK4*512*16 + 512*4 + 512*4 + 2048*4)   // 208896

__global__ __launch_bounds__(512, 1) void lstm_pass(
    const float* __restrict__ gi, const float* __restrict__ masks,
    const float4* __restrict__ wq, float* __restrict__ hout,
    float* __restrict__ hfin, float* __restrict__ cfin)
{
    extern __shared__ float sm[];
    float4* ws = (float4*)sm;              // SK4*512 float4
    float*  hs = sm + SK4 * 512 * 4;       // 512
    float*  cs = hs + 512;                 // 512
    float*  gs = cs + 512;                 // 2048

    const int j  = threadIdx.x;
    const int b0 = blockIdx.x << 2;
    const int r  = j >> 7, u = j & 127;

#pragma unroll
    for (int k4 = 0; k4 < SK4; k4++) ws[k4 * 512 + j] = __ldg(wq + k4 * 512 + j);
    hs[j] = 0.f; cs[j] = 0.f;
    __syncthreads();

    const float* mrow  = masks + (size_t)(b0 + r) * SS;
    float*       hw    = hout + ((size_t)(b0 + r) * SS) * HH + u;
    const float* gbase = gi + ((size_t)b0 * SS) * G4 + j;
    const size_t gstr  = (size_t)SS * G4;
    const float4* hq   = (const float4*)hs;

    float p0 = __ldg(gbase);
    float p1 = __ldg(gbase + gstr);
    float p2 = __ldg(gbase + 2 * gstr);
    float p3 = __ldg(gbase + 3 * gstr);

    for (int t = 0; t < SS; t++) {
        float m = __ldg(mrow + t);
        hs[j] *= m;
        cs[j] *= m;
        __syncthreads();

        float a0 = p0, a1 = p1, a2 = p2, a3 = p3;
        int tn = (t + 1 < SS) ? (t + 1) : t;
        const float* gb = gbase + (size_t)tn * G4;
        p0 = __ldg(gb);
        p1 = __ldg(gb + gstr);
        p2 = __ldg(gb + 2 * gstr);
        p3 = __ldg(gb + 3 * gstr);

#pragma unroll
        for (int k4 = 0; k4 < SK4; k4++) {
            float4 w  = ws[k4 * 512 + j];
            float4 h0 = hq[k4], h1 = hq[32 + k4], h2 = hq[64 + k4], h3 = hq[96 + k4];
            a0 += w.x * h0.x + w.y * h0.y + w.z * h0.z + w.w * h0.w;
            a1 += w.x * h1.x + w.y * h1.y + w.z * h1.z + w.w * h1.w;
            a2 += w.x * h2.x + w.y * h2.y + w.z * h2.z + w.w * h2.w;
            a3 += w.x * h3.x + w.y * h3.y + w.z * h3.z + w.w * h3.w;
        }
#pragma unroll
        for (int k4 = SK4; k4 < 32; k4++) {
            float4 w  = __ldg(wq + k4 * 512 + j);
            float4 h0 = hq[k4], h1 = hq[32 + k4], h2 = hq[64 + k4], h3 = hq[96 + k4];
            a0 += w.x * h0.x + w.y * h0.y + w.z * h0.z + w.w * h0.w;
            a1 += w.x * h1.x + w.y * h1.y + w.z * h1.z + w.w * h1.w;
            a2 += w.x * h2.x + w.y * h2.y + w.z * h2.z + w.w * h2.w;
            a3 += w.x * h3.x + w.y * h3.y + w.z * h3.z + w.w * h3.w;
        }
        gs[j] = a0; gs[512 + j] = a1; gs[1024 + j] = a2; gs[1536 + j] = a3;
        __syncthreads();

        int gb2 = r * 512 + u;
        float xi = gs[gb2], xf = gs[gb2 + 128], xg = gs[gb2 + 256], xo = gs[gb2 + 384];
        float c = sigmf(xf) * cs[j] + sigmf(xi) * tanhf(xg);
        float h = sigmf(xo) * tanhf(c);
        cs[j] = c;
        hs[j] = h;
        hw[(size_t)t * HH] = h;
        // safe: writers of gs in t+1 pass the post-mask __syncthreads first
    }
    hfin[(size_t)(b0 + r) * HH + u] = hs[j];
    cfin[(size_t)(b0 + r) * HH + u] = cs[j];
}

// heads epilogue: 1 thread per (b,s) row
__global__ __launch_bounds__(256) void heads_kernel(
    const float* __restrict__ t1, const float* __restrict__ t2,
    const float* __restrict__ noise,
    const float* __restrict__ am_w2, const float* __restrict__ am_b2,
    const float* __restrict__ log_std,
    const float* __restrict__ cr_w2, const float* __restrict__ cr_b2,
    float* __restrict__ out)
{
    __shared__ float w2s[9 * 64];
    __shared__ float cw[64];
    __shared__ float b2a[9], lsa[9], crb[1];
    int tid = threadIdx.x;
    for (int i = tid; i < 576; i += 256) w2s[i] = __ldg(&am_w2[i]);
    if (tid < 64) cw[tid] = __ldg(&cr_w2[tid]);
    if (tid < 9) {
        b2a[tid] = __ldg(&am_b2[tid]);
        lsa[tid] = fminf(fmaxf(__ldg(&log_std[tid]), -4.f), 0.f);
    }
    if (tid == 0) crb[0] = __ldg(&cr_b2[0]);
    __syncthreads();

    size_t row = (size_t)blockIdx.x * 256 + tid;
    const float4* p1 = (const float4*)(t1 + row * 64);
    const float4* p2 = (const float4*)(t2 + row * 64);
    float mean[9];
#pragma unroll
    for (int a = 0; a < 9; a++) mean[a] = b2a[a];
    float val = crb[0];
#pragma unroll 4
    for (int k4 = 0; k4 < 16; k4++) {
        float4 x1 = __ldg(p1 + k4);
        float4 x2 = __ldg(p2 + k4);
        int k = k4 * 4;
#pragma unroll
        for (int a = 0; a < 9; a++) {
            const float* wr = &w2s[a * 64 + k];
            mean[a] += x1.x * wr[0] + x1.y * wr[1] + x1.z * wr[2] + x1.w * wr[3];
        }
        val += x2.x * cw[k] + x2.y * cw[k+1] + x2.z * cw[k+2] + x2.w * cw[k+3];
    }
    float lp = 0.f;
#pragma unroll
    for (int a = 0; a < 9; a++) {
        float mm = tanhf(mean[a]);
        float ls = lsa[a];
        float sd = expf(ls);
        float nz = __ldg(noise + row * 9 + a);
        float act = mm + sd * nz;
        float z   = (act - mm) / sd;
        lp += -0.5f * z * z - ls;
        out[row * 9 + a] = act;
    }
    lp -= 9.f * 0.9189385332046727f;
    out[OFF_LP + row] = lp;
    out[OFF_V  + row] = val;
}

// ---------------------------------------------------------------------------
extern "C" void kernel_launch(void* const* d_in, const int* in_sizes, int n_in,
                              void* d_out, int out_size)
{
    (void)in_sizes; (void)n_in; (void)out_size;
    const float* obs    = (const float*)d_in[0];
    const float* masks  = (const float*)d_in[1];
    const float* noise  = (const float*)d_in[2];
    const float* enc_w1 = (const float*)d_in[3];
    const float* enc_b1 = (const float*)d_in[4];
    const float* ln_g   = (const float*)d_in[5];
    const float* ln_b   = (const float*)d_in[6];
    const float* enc_w2 = (const float*)d_in[7];
    const float* enc_b2 = (const float*)d_in[8];
    const float* wih0   = (const float*)d_in[9];
    const float* whh0   = (const float*)d_in[10];
    const float* bih0   = (const float*)d_in[11];
    const float* bhh0   = (const float*)d_in[12];
    const float* wih1   = (const float*)d_in[13];
    const float* whh1   = (const float*)d_in[14];
    const float* bih1   = (const float*)d_in[15];
    const float* bhh1   = (const float*)d_in[16];
    const float* am_w1  = (const float*)d_in[17];
    const float* am_b1  = (const float*)d_in[18];
    const float* am_w2  = (const float*)d_in[19];
    const float* am_b2  = (const float*)d_in[20];
    const float* log_std= (const float*)d_in[21];
    const float* cr_w1  = (const float*)d_in[22];
    const float* cr_b1  = (const float*)d_in[23];
    const float* cr_w2  = (const float*)d_in[24];
    const float* cr_b2  = (const float*)d_in[25];
    float* out = (float*)d_out;

    float *A, *Bf, *Cf; float4 *wq;
    cudaGetSymbolAddress((void**)&A,  g_A);
    cudaGetSymbolAddress((void**)&Bf, g_Bf);
    cudaGetSymbolAddress((void**)&Cf, g_Cf);
    cudaGetSymbolAddress((void**)&wq, g_wq);

    cudaFuncSetAttribute(lstm_pass,
        cudaFuncAttributeMaxDynamicSharedMemorySize, PASS_SMEM);

    // pack whh for both layers
    pack_whh<<<64, 256>>>(whh0, wq);
    pack_whh<<<64, 256>>>(whh1, wq + 32 * 512);

    dim3 gM2(2, 2048), gM8(8, 2048), gM1(1, 2048);
    // encoder
    gemm_kernel<<<gM2, 256>>>(obs, enc_w1, enc_b1, nullptr, Bf,
                              M_ROWS, 128, 64, 0);
    ln_relu_kernel<<<M_ROWS / 8, 256>>>(Bf, Cf, ln_g, ln_b);
    gemm_kernel<<<gM2, 256>>>(Cf, enc_w2, enc_b2, nullptr, Bf,
                              M_ROWS, 128, 128, 1);
    // layer 0
    gemm_kernel<<<gM8, 256>>>(Bf, wih0, bih0, bhh0, A,
                              M_ROWS, 512, 128, 0);
    lstm_pass<<<128, 512, PASS_SMEM>>>(A, masks, wq, Cf,
                                       out + OFF_H, out + OFF_C);
    // layer 1
    gemm_kernel<<<gM8, 256>>>(Cf, wih1, bih1, bhh1, A,
                              M_ROWS, 512, 128, 0);
    lstm_pass<<<128, 512, PASS_SMEM>>>(A, masks, wq + 32 * 512, Bf,
                                       out + OFF_H + (size_t)BB * HH,
                                       out + OFF_C + (size_t)BB * HH);
    // heads: t1 (actor hidden) and t2 (critic hidden), both M x 64
    gemm_kernel<<<gM1, 256>>>(Bf, am_w1, am_b1, nullptr, Cf,
                              M_ROWS, 64, 128, 1);
    gemm_kernel<<<gM1, 256>>>(Bf, cr_w1, cr_b1, nullptr, Cf + (size_t)M_ROWS * 64,
                              M_ROWS, 64, 128, 1);
    heads_kernel<<<M_ROWS / 256, 256>>>(Cf, Cf + (size_t)M_ROWS * 64, noise,
                                        am_w2, am_b2, log_std, cr_w2, cr_b2, out);
}